// round 16
// baseline (speedup 1.0000x reference)
#include <cuda_runtime.h>
#include <math.h>
#include <stdint.h>

#define HID 256
#define NSTEPS 100
#define MAXRAYS 4096
#define SDF_THR 5e-5f
#define EVAL_THREADS 256   // one W2 column per thread
#define TRACE_ITERS 10
#define TRACE_SPLIT 4      // iterations in phase A (0..TRACE_SPLIT-1), rest in B
#define SECANT_ITERS 8
#define TPA 16    // points/block phase A (bandwidth-friendly, all rays active)
#define TPB 8     // points/block phase B (compacted actives)
#define TPS 32    // points/block sampler

// ---------------- device scratch (no allocations allowed) ----------------
__device__ int   g_mask_mode;   // 0=int32, 1=float32, 2=uint8/bool
__device__ int   g_scount;      // # sampler rays
__device__ int   g_seccount;    // # secant rays
__device__ int   g_tcount;      // # active rays after phase A
__device__ float g_acc[MAXRAYS];
__device__ float g_accend[MAXRAYS];
__device__ float g_nextsdf[MAXRAYS];
__device__ unsigned char g_unf[MAXRAYS];
__device__ int   g_tlist[MAXRAYS];
__device__ int   g_slist[MAXRAYS];
__device__ int   g_seclist[MAXRAYS];
__device__ float g_zl[MAXRAYS], g_zh[MAXRAYS], g_sl[MAXRAYS], g_shh[MAXRAYS];
__device__ float g_sdf100[MAXRAYS * NSTEPS];

// ---------------- exact-rounding helpers (block nvcc fma contraction) -----
__device__ __forceinline__ float mulrn(float a, float b) { return __fmul_rn(a, b); }
__device__ __forceinline__ float addrn(float a, float b) { return __fadd_rn(a, b); }
__device__ __forceinline__ float subrn(float a, float b) { return __fsub_rn(a, b); }
__device__ __forceinline__ float divrn(float a, float b) { return __fdiv_rn(a, b); }

__device__ __forceinline__ float softplus_f(float x) {
    // jax.nn.softplus = logaddexp(x, 0) = max(x,0) + log1p(exp(-|x|))
    return addrn(fmaxf(x, 0.0f), log1pf(expf(-fabsf(x))));
}

__device__ __forceinline__ float lin_t(int i) {
    return (i == NSTEPS - 1) ? 1.0f : mulrn((float)i, 1.0f / 99.0f);
}

__device__ __forceinline__ float ray_pt(float c, float d, float dir) {
    return addrn(c, mulrn(d, dir));
}

__device__ __forceinline__ bool read_mask(const void* p, int i) {
    int mode = g_mask_mode;
    if (mode == 0) return ((const int*)p)[i] != 0;
    if (mode == 1) return ((const float*)p)[i] != 0.0f;
    return ((const unsigned char*)p)[i] != 0;
}

// Block-cooperative SDF eval of TPP points. blockDim.x must be 256;
// thread t owns W2 column j=t. Per-column accumulation order
// (ascending-k single-accumulator fmaf chain) is unchanged vs prior rounds
// -> bit-identical numerics for any TPP / DEEP config.
template<int TPP, bool DEEP>
__device__ void sdf_eval_block(const float4* __restrict__ sh_pts,
                               float* __restrict__ sh_buf,       // HID*(TPP+1) floats
                               const float* __restrict__ sh_w3,  // 256 floats
                               float* __restrict__ sh_out,       // TPP floats
                               const float* __restrict__ W1, const float* __restrict__ b1,
                               const float* __restrict__ W2, const float* __restrict__ b2,
                               const float* __restrict__ b3p)
{
    const int t = threadIdx.x;
    const int j = t;
    const int H2S = TPP + 1;

    // ---- layer 1: h1 = softplus((p @ W1) + b1); ascending-k fma chain ----
    {
        float w1x = W1[j], w1y = W1[HID + j], w1z = W1[2 * HID + j], bb = b1[j];
        #pragma unroll
        for (int p = 0; p < TPP; p++) {
            float4 q = sh_pts[p];
            float d = fmaf(q.z, w1z, fmaf(q.y, w1y, mulrn(q.x, w1x)));
            sh_buf[p * HID + j] = softplus_f(addrn(d, bb));
        }
    }
    __syncthreads();

    // ---- layer 2: acc = h1 @ W2; single accumulator, ascending k, fmaf ----
    float acc[TPP];
    #pragma unroll
    for (int p = 0; p < TPP; p++) acc[p] = 0.0f;

    if (DEEP) {
        // 8-row current window, 8-row lookahead (16 weight regs)
        float A0 = W2[0 * HID + j], A1 = W2[1 * HID + j], A2 = W2[2 * HID + j], A3 = W2[3 * HID + j];
        float B0 = W2[4 * HID + j], B1 = W2[5 * HID + j], B2 = W2[6 * HID + j], B3 = W2[7 * HID + j];
        #pragma unroll 1
        for (int k = 0; k < HID; k += 8) {
            float nA0 = 0.f, nA1 = 0.f, nA2 = 0.f, nA3 = 0.f;
            if (k + 8 < HID) {
                nA0 = W2[(k + 8) * HID + j];  nA1 = W2[(k + 9) * HID + j];
                nA2 = W2[(k + 10) * HID + j]; nA3 = W2[(k + 11) * HID + j];
            }
            #pragma unroll
            for (int p = 0; p < TPP; p++) {
                float4 h = *reinterpret_cast<const float4*>(sh_buf + p * HID + k);
                float s = acc[p];
                s = fmaf(h.x, A0, s);
                s = fmaf(h.y, A1, s);
                s = fmaf(h.z, A2, s);
                s = fmaf(h.w, A3, s);
                acc[p] = s;
            }
            float nB0 = 0.f, nB1 = 0.f, nB2 = 0.f, nB3 = 0.f;
            if (k + 12 < HID) {
                nB0 = W2[(k + 12) * HID + j]; nB1 = W2[(k + 13) * HID + j];
                nB2 = W2[(k + 14) * HID + j]; nB3 = W2[(k + 15) * HID + j];
            }
            #pragma unroll
            for (int p = 0; p < TPP; p++) {
                float4 h = *reinterpret_cast<const float4*>(sh_buf + p * HID + k + 4);
                float s = acc[p];
                s = fmaf(h.x, B0, s);
                s = fmaf(h.y, B1, s);
                s = fmaf(h.z, B2, s);
                s = fmaf(h.w, B3, s);
                acc[p] = s;
            }
            A0 = nA0; A1 = nA1; A2 = nA2; A3 = nA3;
            B0 = nB0; B1 = nB1; B2 = nB2; B3 = nB3;
        }
    } else {
        float a0 = W2[0 * HID + j], a1 = W2[1 * HID + j], a2 = W2[2 * HID + j], a3 = W2[3 * HID + j];
        #pragma unroll 1
        for (int k = 0; k < HID; k += 4) {
            float na0 = 0.f, na1 = 0.f, na2 = 0.f, na3 = 0.f;
            if (k + 4 < HID) {
                na0 = W2[(k + 4) * HID + j]; na1 = W2[(k + 5) * HID + j];
                na2 = W2[(k + 6) * HID + j]; na3 = W2[(k + 7) * HID + j];
            }
            #pragma unroll
            for (int p = 0; p < TPP; p++) {
                float4 h = *reinterpret_cast<const float4*>(sh_buf + p * HID + k);
                float s = acc[p];
                s = fmaf(h.x, a0, s);
                s = fmaf(h.y, a1, s);
                s = fmaf(h.z, a2, s);
                s = fmaf(h.w, a3, s);
                acc[p] = s;
            }
            a0 = na0; a1 = na1; a2 = na2; a3 = na3;
        }
    }
    __syncthreads();

    // ---- epilogue: h2 = softplus(acc + b2), stored TRANSPOSED (stride TPP+1) ----
    {
        float b2j = b2[j];
        #pragma unroll
        for (int p = 0; p < TPP; p++)
            sh_buf[j * H2S + p] = softplus_f(addrn(acc[p], b2j));
    }
    __syncthreads();

    // ---- w3 dot: strict ascending-k fmaf chain (one thread per point) ----
    if (t < TPP) {
        const int p = t;
        float s = 0.0f;
        #pragma unroll 8
        for (int jj = 0; jj < HID; jj++)
            s = fmaf(sh_buf[jj * H2S + p], sh_w3[jj], s);
        float inner = mulrn(0.1f, addrn(s, b3p[0]));
        float4 q = sh_pts[p];
        float n2 = addrn(addrn(addrn(mulrn(q.x, q.x), mulrn(q.y, q.y)),
                               mulrn(q.z, q.z)), 1e-12f);
        sh_out[p] = addrn(subrn(sqrtf(n2), 0.9f), inner);
    }
    __syncthreads();
}

#define DECLARE_EVAL_SMEM(TPP)                                    \
    __shared__ float4 sh_pts[TPP];                                \
    __shared__ __align__(16) float sh_buf[HID * ((TPP) + 1)];     \
    __shared__ float sh_w3[HID];                                  \
    __shared__ float sh_sdf[TPP];

#define LOAD_W3()  do { sh_w3[threadIdx.x] = w3[threadIdx.x]; } while (0)

// shared body of one tracing iteration (templated on tile size)
template<int TPP>
__device__ __forceinline__ void trace_one_iter(
    bool vr, int& unf, float& acc, float accend, float& nsdf,
    float cx, float cy, float cz, float dx, float dy, float dz,
    float4* sh_pts, float* sh_buf, const float* sh_w3, float* sh_sdf,
    int* sh_flag, bool& block_done,
    const float* W1, const float* b1, const float* W2, const float* b2,
    const float* b3p)
{
    const int t = threadIdx.x;
    __syncthreads();
    if (t < 2) sh_flag[t] = 0;
    __syncthreads();

    float csdf = 0.f; int notproj = 0;
    if (vr) {
        csdf = unf ? nsdf : 0.0f;
        if (csdf <= SDF_THR) csdf = 0.0f;
        unf = unf && (csdf > SDF_THR);
        acc = addrn(acc, csdf);
        sh_pts[t] = make_float4(ray_pt(cx, acc, dx), ray_pt(cy, acc, dy),
                                ray_pt(cz, acc, dz), 0.0f);
        if (unf) atomicOr(&sh_flag[0], 1);
    }
    __syncthreads();
    if (!sh_flag[0]) { block_done = true; return; }

    sdf_eval_block<TPP, true>(sh_pts, sh_buf, sh_w3, sh_sdf, W1, b1, W2, b2, b3p);

    if (vr) {
        nsdf = unf ? sh_sdf[t] : 0.0f;
        notproj = (nsdf < 0.0f) ? 1 : 0;
        if (notproj) {
            acc = subrn(acc, mulrn(0.5f, csdf));
            sh_pts[t] = make_float4(ray_pt(cx, acc, dx), ray_pt(cy, acc, dy),
                                    ray_pt(cz, acc, dz), 0.0f);
            atomicOr(&sh_flag[1], 1);
        }
    }
    __syncthreads();

    if (sh_flag[1]) {
        sdf_eval_block<TPP, true>(sh_pts, sh_buf, sh_w3, sh_sdf, W1, b1, W2, b2, b3p);
        if (vr && notproj) nsdf = sh_sdf[t];
    }
    if (vr) unf = unf && (acc < accend);
}

// ---------------- kernels ----------------

// zero counters + detect object_mask dtype from byte patterns
__global__ void reset_kernel(const unsigned char* __restrict__ mb, int nelem) {
    __shared__ int s_nonalign, s_floatok;
    if (threadIdx.x == 0) {
        s_nonalign = 0; s_floatok = 1;
        g_scount = 0; g_seccount = 0; g_tcount = 0;
    }
    __syncthreads();
    int nwords = nelem >> 2;
    const unsigned int* w = (const unsigned int*)mb;
    for (int i = threadIdx.x; i < nwords; i += blockDim.x) {
        unsigned int v = w[i];
        if (v & 0xFFFFFF00u) atomicOr(&s_nonalign, 1);
        if (!(v == 0u || v == 0x3F800000u)) atomicAnd(&s_floatok, 0);
    }
    __syncthreads();
    if (threadIdx.x == 0)
        g_mask_mode = (!s_nonalign) ? 0 : (s_floatok ? 1 : 2);
}

// PHASE A: sphere intersection + initial eval + iterations 0..TRACE_SPLIT-1.
__global__ void __launch_bounds__(EVAL_THREADS, 4)
trace_phaseA_kernel(const float* __restrict__ cam, const float* __restrict__ dirs,
                    const float* __restrict__ W1, const float* __restrict__ b1,
                    const float* __restrict__ W2, const float* __restrict__ b2,
                    const float* __restrict__ w3, const float* __restrict__ b3p,
                    int bn, int nper)
{
    DECLARE_EVAL_SMEM(TPA);
    __shared__ int sh_flag[2];
    const int t = threadIdx.x;
    const int r = blockIdx.x * TPA + t;
    const bool vr = (t < TPA) && (r < bn);
    LOAD_W3();
    if (t < 2) sh_flag[t] = 0;
    __syncthreads();

    int unf = 0;
    float acc = 0.f, accend = 0.f, nsdf = 0.f;
    float cx = 0.f, cy = 0.f, cz = 0.f, dx = 0.f, dy = 0.f, dz = 0.f;

    if (t < TPA) {
        if (vr) {
            int b = r / nper;
            cx = cam[b * 3]; cy = cam[b * 3 + 1]; cz = cam[b * 3 + 2];
            dx = dirs[r * 3]; dy = dirs[r * 3 + 1]; dz = dirs[r * 3 + 2];
            float dot = addrn(addrn(mulrn(dx, cx), mulrn(dy, cy)), mulrn(dz, cz));
            float c2  = addrn(addrn(mulrn(cx, cx), mulrn(cy, cy)), mulrn(cz, cz));
            float under = subrn(mulrn(dot, dot), subrn(c2, 1.0f));   // R = 1
            int m = (under > 0.0f) ? 1 : 0;
            float d0 = 0.0f, d1 = 0.0f;
            if (m) {
                float s = sqrtf(under);
                d0 = fmaxf(subrn(-s, dot), 0.0f);
                d1 = fmaxf(subrn( s, dot), 0.0f);
            }
            unf = m; acc = d0; accend = d1;
            sh_pts[t] = m ? make_float4(ray_pt(cx, d0, dx), ray_pt(cy, d0, dy),
                                        ray_pt(cz, d0, dz), 0.0f)
                          : make_float4(0.0f, 0.0f, 0.0f, 0.0f);
            if (m) atomicOr(&sh_flag[0], 1);
        } else {
            sh_pts[t] = make_float4(0.0f, 0.0f, 0.0f, 0.0f);
        }
    }
    __syncthreads();
    if (sh_flag[0]) sdf_eval_block<TPA, true>(sh_pts, sh_buf, sh_w3, sh_sdf, W1, b1, W2, b2, b3p);
    if (vr) nsdf = unf ? sh_sdf[t] : 0.0f;

    bool block_done = false;
    for (int it = 0; it < TRACE_SPLIT && !block_done; ++it)
        trace_one_iter<TPA>(vr, unf, acc, accend, nsdf, cx, cy, cz, dx, dy, dz,
                            sh_pts, sh_buf, sh_w3, sh_sdf, sh_flag, block_done,
                            W1, b1, W2, b2, b3p);

    if (vr) {
        g_acc[r] = acc;
        g_accend[r] = accend;
        g_nextsdf[r] = nsdf;
        g_unf[r] = (unsigned char)unf;
    }
}

// compact surviving active rays into g_tlist
__global__ void trace_compact_kernel(int bn) {
    int r = blockIdx.x * blockDim.x + threadIdx.x;
    if (r >= bn) return;
    if (g_unf[r]) {
        int pos = atomicAdd(&g_tcount, 1);
        g_tlist[pos] = r;
    }
}

// PHASE B: iterations TRACE_SPLIT..TRACE_ITERS-1 on packed active list.
__global__ void __launch_bounds__(EVAL_THREADS, 4)
trace_phaseB_kernel(const float* __restrict__ cam, const float* __restrict__ dirs,
                    const float* __restrict__ W1, const float* __restrict__ b1,
                    const float* __restrict__ W2, const float* __restrict__ b2,
                    const float* __restrict__ w3, const float* __restrict__ b3p,
                    int nper)
{
    int cnt = g_tcount;
    int base = blockIdx.x * TPB;
    if (base >= cnt) return;   // uniform early exit
    DECLARE_EVAL_SMEM(TPB);
    __shared__ int sh_flag[2];
    const int t = threadIdx.x;
    LOAD_W3();
    if (t < 2) sh_flag[t] = 0;
    __syncthreads();

    bool vr = false;
    int r = 0, unf = 0;
    float acc = 0.f, accend = 0.f, nsdf = 0.f;
    float cx = 0.f, cy = 0.f, cz = 0.f, dx = 0.f, dy = 0.f, dz = 0.f;

    if (t < TPB) {
        int idx = base + t;
        vr = idx < cnt;
        if (vr) {
            r = g_tlist[idx];
            unf = 1;                         // list holds only unfinished rays
            acc = g_acc[r]; accend = g_accend[r]; nsdf = g_nextsdf[r];
            int b = r / nper;
            cx = cam[b * 3]; cy = cam[b * 3 + 1]; cz = cam[b * 3 + 2];
            dx = dirs[r * 3]; dy = dirs[r * 3 + 1]; dz = dirs[r * 3 + 2];
        }
    }

    bool block_done = false;
    for (int it = TRACE_SPLIT; it < TRACE_ITERS && !block_done; ++it)
        trace_one_iter<TPB>(vr, unf, acc, accend, nsdf, cx, cy, cz, dx, dy, dz,
                            sh_pts, sh_buf, sh_w3, sh_sdf, sh_flag, block_done,
                            W1, b1, W2, b2, b3p);

    if (vr) {
        g_acc[r] = acc;
        g_nextsdf[r] = nsdf;
        g_unf[r] = (unsigned char)unf;
    }
}

// final mask update, base outputs, sampler-ray compaction
__global__ void finalize_kernel(const float* __restrict__ cam, const float* __restrict__ dirs,
                                float* __restrict__ out_pts, float* __restrict__ out_mask,
                                float* __restrict__ out_dist, int bn, int nper)
{
    int r = blockIdx.x * blockDim.x + threadIdx.x;
    if (r >= bn) return;
    int unf = g_unf[r];
    float cs = unf ? g_nextsdf[r] : 0.0f;
    if (cs <= SDF_THR) cs = 0.0f;
    unf = unf && (cs > SDF_THR);
    float a = g_acc[r], e = g_accend[r];
    int b = r / nper;
    float cx = cam[b * 3], cy = cam[b * 3 + 1], cz = cam[b * 3 + 2];
    float dx = dirs[r * 3], dy = dirs[r * 3 + 1], dz = dirs[r * 3 + 2];
    out_pts[r * 3 + 0] = ray_pt(cx, a, dx);
    out_pts[r * 3 + 1] = ray_pt(cy, a, dy);
    out_pts[r * 3 + 2] = ray_pt(cz, a, dz);
    out_mask[r] = (a < e) ? 1.0f : 0.0f;
    out_dist[r] = a;
    if (unf) {
        int pos = atomicAdd(&g_scount, 1);
        g_slist[pos] = r;
    }
}

// evaluate sdf on the 100-step march of every sampler ray (compacted)
__global__ void __launch_bounds__(EVAL_THREADS, 3)
sampler_eval_kernel(const float* __restrict__ cam, const float* __restrict__ dirs,
                    const float* __restrict__ W1, const float* __restrict__ b1,
                    const float* __restrict__ W2, const float* __restrict__ b2,
                    const float* __restrict__ w3, const float* __restrict__ b3p,
                    int nper)
{
    int total = g_scount * NSTEPS;
    int base = blockIdx.x * TPS;
    if (base >= total) return;  // uniform across the block
    DECLARE_EVAL_SMEM(TPS);
    int t = threadIdx.x;
    int q = base + t;
    bool valid = false;
    LOAD_W3();
    if (t < TPS) {
        valid = q < total;
        if (valid) {
            int slot = q / NSTEPS;
            int s = q - slot * NSTEPS;
            int r = g_slist[slot];
            float a = g_acc[r], e = g_accend[r];
            float d = addrn(a, mulrn(lin_t(s), subrn(e, a)));
            int b = r / nper;
            sh_pts[t] = make_float4(ray_pt(cam[b * 3 + 0], d, dirs[r * 3 + 0]),
                                    ray_pt(cam[b * 3 + 1], d, dirs[r * 3 + 1]),
                                    ray_pt(cam[b * 3 + 2], d, dirs[r * 3 + 2]), 0.0f);
        } else {
            sh_pts[t] = make_float4(0.0f, 0.0f, 0.0f, 0.0f);
        }
    }
    __syncthreads();
    sdf_eval_block<TPS, false>(sh_pts, sh_buf, sh_w3, sh_sdf, W1, b1, W2, b2, b3p);
    if (t < TPS && valid) g_sdf100[q] = sh_sdf[t];
}

// argmin selection, sampler outputs, secant-ray compaction
__global__ void select_kernel(const float* __restrict__ cam, const float* __restrict__ dirs,
                              const void* __restrict__ omask,
                              float* __restrict__ out_pts, float* __restrict__ out_mask,
                              float* __restrict__ out_dist, int nper)
{
    int cnt = g_scount;
    for (int slot = blockIdx.x * blockDim.x + threadIdx.x; slot < cnt;
         slot += gridDim.x * blockDim.x) {
        int r = g_slist[slot];
        const float* base = &g_sdf100[slot * NSTEPS];
        float bestt = 1e30f; int ind = 0;
        float bestv = 1e30f; int oind = 0;
        for (int i = 0; i < NSTEPS; i++) {
            float v = base[i];
            float sgn = (v > 0.0f) ? 1.0f : ((v < 0.0f) ? -1.0f : 0.0f);
            float tmp = sgn * (float)(NSTEPS - i);
            if (tmp < bestt) { bestt = tmp; ind = i; }      // first-occurrence argmin
            if (v   < bestv) { bestv = v;   oind = i; }
        }
        bool net = base[ind] < 0.0f;
        bool obj = read_mask(omask, r);
        bool p_out = !(obj && net);
        int ind2 = p_out ? oind : ind;
        float a = g_acc[r], e = g_accend[r];
        int b = r / nper;
        float cx = cam[b * 3], cy = cam[b * 3 + 1], cz = cam[b * 3 + 2];
        float dx = dirs[r * 3], dy = dirs[r * 3 + 1], dz = dirs[r * 3 + 2];
        float d2 = addrn(a, mulrn(lin_t(ind2), subrn(e, a)));
        out_pts[r * 3 + 0] = ray_pt(cx, d2, dx);
        out_pts[r * 3 + 1] = ray_pt(cy, d2, dy);
        out_pts[r * 3 + 2] = ray_pt(cz, d2, dz);
        out_dist[r] = d2;
        out_mask[r] = net ? 1.0f : 0.0f;
        if (net && obj) {
            int im1 = (ind == 0) ? (NSTEPS - 1) : (ind - 1);   // torch (-1) wrap
            g_zh[r]  = addrn(a, mulrn(lin_t(ind), subrn(e, a)));
            g_shh[r] = base[ind];
            g_zl[r]  = addrn(a, mulrn(lin_t(im1), subrn(e, a)));
            g_sl[r]  = base[im1];
            int pos = atomicAdd(&g_seccount, 1);
            g_seclist[pos] = r;
        }
    }
}

// FUSED: all 8 secant iterations in one kernel (blocks over compacted rays)
__global__ void __launch_bounds__(EVAL_THREADS, 4)
secant_fused_kernel(const float* __restrict__ cam, const float* __restrict__ dirs,
                    const float* __restrict__ W1, const float* __restrict__ b1,
                    const float* __restrict__ W2, const float* __restrict__ b2,
                    const float* __restrict__ w3, const float* __restrict__ b3p,
                    float* __restrict__ out_pts, float* __restrict__ out_dist,
                    int nper)
{
    int cnt = g_seccount;
    int base = blockIdx.x * TPB;
    if (base >= cnt) return;  // uniform
    DECLARE_EVAL_SMEM(TPB);
    int t = threadIdx.x;
    bool valid = false;
    int r = 0;
    float zl = 0.f, zh = 0.f, sl = 0.f, shv = 0.f;
    float cx = 0.f, cy = 0.f, cz = 0.f, dx = 0.f, dy = 0.f, dz = 0.f;
    LOAD_W3();
    if (t < TPB) {
        int idx = base + t;
        valid = idx < cnt;
        if (valid) {
            r = g_seclist[idx];
            zl = g_zl[r]; zh = g_zh[r]; sl = g_sl[r]; shv = g_shh[r];
            int b = r / nper;
            cx = cam[b * 3]; cy = cam[b * 3 + 1]; cz = cam[b * 3 + 2];
            dx = dirs[r * 3]; dy = dirs[r * 3 + 1]; dz = dirs[r * 3 + 2];
        }
        sh_pts[t] = make_float4(0.0f, 0.0f, 0.0f, 0.0f);
    }

    for (int it = 0; it < SECANT_ITERS; ++it) {
        float zp = 0.f;
        if (valid) {
            float den = subrn(shv, sl);
            if (den == 0.0f) den = 1.0f;
            zp = addrn(divrn(mulrn(-sl, subrn(zh, zl)), den), zl);
            sh_pts[t] = make_float4(ray_pt(cx, zp, dx), ray_pt(cy, zp, dy),
                                    ray_pt(cz, zp, dz), 0.0f);
        }
        __syncthreads();
        sdf_eval_block<TPB, true>(sh_pts, sh_buf, sh_w3, sh_sdf, W1, b1, W2, b2, b3p);
        if (valid) {
            float mid = sh_sdf[t];
            if (mid > 0.0f) { zl = zp; sl = mid; }
            if (mid < 0.0f) { zh = zp; shv = mid; }
        }
    }

    // final secant prediction + output override
    if (valid) {
        float den = subrn(shv, sl);
        if (den == 0.0f) den = 1.0f;
        float zp = addrn(divrn(mulrn(-sl, subrn(zh, zl)), den), zl);
        out_pts[r * 3 + 0] = ray_pt(cx, zp, dx);
        out_pts[r * 3 + 1] = ray_pt(cy, zp, dy);
        out_pts[r * 3 + 2] = ray_pt(cz, zp, dz);
        out_dist[r] = zp;
    }
}

// ---------------- host launcher ----------------
extern "C" void kernel_launch(void* const* d_in, const int* in_sizes, int n_in,
                              void* d_out, int out_size)
{
    const float* cam  = (const float*)d_in[0];
    const void*  om   = d_in[1];
    const float* dirs = (const float*)d_in[2];
    const float* W1   = (const float*)d_in[3];
    const float* b1   = (const float*)d_in[4];
    const float* W2   = (const float*)d_in[5];
    const float* b2   = (const float*)d_in[6];
    const float* w3   = (const float*)d_in[7];
    const float* b3   = (const float*)d_in[8];

    int bn   = in_sizes[2] / 3;        // total rays (B*N)
    int ncam = in_sizes[0] / 3;        // B
    int nper = bn / ncam;              // N

    float* out      = (float*)d_out;
    float* out_pts  = out;             // [bn,3]
    float* out_mask = out + 3 * bn;    // [bn]
    float* out_dist = out + 4 * bn;    // [bn]

    int nba = (bn + TPA - 1) / TPA;    // phase A blocks (256)
    int nbb = (bn + TPB - 1) / TPB;    // phase B / secant max blocks (512)

    reset_kernel<<<1, 256>>>((const unsigned char*)om, bn);
    trace_phaseA_kernel<<<nba, EVAL_THREADS>>>(cam, dirs, W1, b1, W2, b2, w3, b3, bn, nper);
    trace_compact_kernel<<<(bn + 255) / 256, 256>>>(bn);
    trace_phaseB_kernel<<<nbb, EVAL_THREADS>>>(cam, dirs, W1, b1, W2, b2, w3, b3, nper);
    finalize_kernel<<<(bn + 255) / 256, 256>>>(cam, dirs, out_pts, out_mask, out_dist, bn, nper);

    int nsb = (bn * NSTEPS + TPS - 1) / TPS;   // max sampler blocks; early-exit on count
    sampler_eval_kernel<<<nsb, EVAL_THREADS>>>(cam, dirs, W1, b1, W2, b2, w3, b3, nper);
    select_kernel<<<32, 128>>>(cam, dirs, om, out_pts, out_mask, out_dist, nper);

    secant_fused_kernel<<<nbb, EVAL_THREADS>>>(cam, dirs, W1, b1, W2, b2, w3, b3,
                                               out_pts, out_dist, nper);
}

// round 17
// speedup vs baseline: 1.3765x; 1.3765x over previous
#include <cuda_runtime.h>
#include <math.h>
#include <stdint.h>

#define HID 256
#define NSTEPS 100
#define MAXRAYS 4096
#define SDF_THR 5e-5f
#define EVAL_THREADS 128   // two W2 columns per thread (best known config)
#define TRACE_ITERS 10
#define TRACE_SPLIT 4      // iterations in phase A (0..TRACE_SPLIT-1), rest in B
#define SECANT_ITERS 8
#define TPA 16    // points/block phase A
#define TPB 8     // points/block phase B
#define SECTP 4   // points/block secant (short serial chain -> small tile)
#define TPS 32    // points/block sampler

// ---------------- device scratch (no allocations allowed) ----------------
__device__ int   g_mask_mode;   // 0=int32, 1=float32, 2=uint8/bool
__device__ int   g_scount;      // # sampler rays
__device__ int   g_seccount;    // # secant rays
__device__ int   g_tcount;      // # active rays after phase A
__device__ float g_acc[MAXRAYS];
__device__ float g_accend[MAXRAYS];
__device__ float g_nextsdf[MAXRAYS];
__device__ unsigned char g_unf[MAXRAYS];
__device__ int   g_tlist[MAXRAYS];
__device__ int   g_slist[MAXRAYS];
__device__ int   g_seclist[MAXRAYS];
__device__ float g_zl[MAXRAYS], g_zh[MAXRAYS], g_sl[MAXRAYS], g_shh[MAXRAYS];
__device__ float g_sdf100[MAXRAYS * NSTEPS];

// ---------------- exact-rounding helpers (block nvcc fma contraction) -----
__device__ __forceinline__ float mulrn(float a, float b) { return __fmul_rn(a, b); }
__device__ __forceinline__ float addrn(float a, float b) { return __fadd_rn(a, b); }
__device__ __forceinline__ float subrn(float a, float b) { return __fsub_rn(a, b); }
__device__ __forceinline__ float divrn(float a, float b) { return __fdiv_rn(a, b); }

__device__ __forceinline__ float softplus_f(float x) {
    // jax.nn.softplus = logaddexp(x, 0) = max(x,0) + log1p(exp(-|x|))
    return addrn(fmaxf(x, 0.0f), log1pf(expf(-fabsf(x))));
}

__device__ __forceinline__ float lin_t(int i) {
    return (i == NSTEPS - 1) ? 1.0f : mulrn((float)i, 1.0f / 99.0f);
}

__device__ __forceinline__ float ray_pt(float c, float d, float dir) {
    return addrn(c, mulrn(d, dir));
}

__device__ __forceinline__ bool read_mask(const void* p, int i) {
    int mode = g_mask_mode;
    if (mode == 0) return ((const int*)p)[i] != 0;
    if (mode == 1) return ((const float*)p)[i] != 0.0f;
    return ((const unsigned char*)p)[i] != 0;
}

// Block-cooperative SDF eval of TPP points. blockDim.x must be 128; thread t
// owns W2 columns t and t+128. Per-column accumulation order (ascending-k
// single-accumulator fmaf chain) is independent of TPP/DEEP -> bit-identical
// numerics for any tile size, so runtime dispatch on active count is safe.
template<int TPP, bool DEEP>
__device__ void sdf_eval_block(const float4* __restrict__ sh_pts,
                               float* __restrict__ sh_buf,       // >= HID*(TPP+1) floats
                               const float* __restrict__ sh_w3,  // 256 floats
                               float* __restrict__ sh_out,       // TPP floats
                               const float* __restrict__ W1, const float* __restrict__ b1,
                               const float* __restrict__ W2, const float* __restrict__ b2,
                               const float* __restrict__ b3p)
{
    const int t  = threadIdx.x;
    const int j0 = t;
    const int j1 = t + EVAL_THREADS;
    const int H2S = TPP + 1;

    // ---- layer 1: h1 = softplus((p @ W1) + b1); ascending-k fma chain ----
    {
        float w1x0 = W1[j0], w1y0 = W1[HID + j0], w1z0 = W1[2 * HID + j0], bb0 = b1[j0];
        float w1x1 = W1[j1], w1y1 = W1[HID + j1], w1z1 = W1[2 * HID + j1], bb1 = b1[j1];
        #pragma unroll
        for (int p = 0; p < TPP; p++) {
            float4 q = sh_pts[p];
            float d0 = fmaf(q.z, w1z0, fmaf(q.y, w1y0, mulrn(q.x, w1x0)));
            float d1 = fmaf(q.z, w1z1, fmaf(q.y, w1y1, mulrn(q.x, w1x1)));
            sh_buf[p * HID + j0] = softplus_f(addrn(d0, bb0));
            sh_buf[p * HID + j1] = softplus_f(addrn(d1, bb1));
        }
    }
    __syncthreads();

    // ---- layer 2: acc = h1 @ W2; single accumulator, ascending k, fmaf ----
    float acc0[TPP], acc1[TPP];
    #pragma unroll
    for (int p = 0; p < TPP; p++) { acc0[p] = 0.0f; acc1[p] = 0.0f; }

    if (DEEP) {
        // two-group (8-row) software pipeline
        float A0 = W2[0 * HID + j0], A1 = W2[1 * HID + j0], A2 = W2[2 * HID + j0], A3 = W2[3 * HID + j0];
        float C0 = W2[0 * HID + j1], C1 = W2[1 * HID + j1], C2 = W2[2 * HID + j1], C3 = W2[3 * HID + j1];
        float B0 = W2[4 * HID + j0], B1 = W2[5 * HID + j0], B2 = W2[6 * HID + j0], B3 = W2[7 * HID + j0];
        float D0 = W2[4 * HID + j1], D1 = W2[5 * HID + j1], D2 = W2[6 * HID + j1], D3 = W2[7 * HID + j1];
        #pragma unroll 1
        for (int k = 0; k < HID; k += 8) {
            float nA0 = 0.f, nA1 = 0.f, nA2 = 0.f, nA3 = 0.f;
            float nC0 = 0.f, nC1 = 0.f, nC2 = 0.f, nC3 = 0.f;
            if (k + 8 < HID) {
                nA0 = W2[(k + 8) * HID + j0];  nA1 = W2[(k + 9) * HID + j0];
                nA2 = W2[(k + 10) * HID + j0]; nA3 = W2[(k + 11) * HID + j0];
                nC0 = W2[(k + 8) * HID + j1];  nC1 = W2[(k + 9) * HID + j1];
                nC2 = W2[(k + 10) * HID + j1]; nC3 = W2[(k + 11) * HID + j1];
            }
            #pragma unroll
            for (int p = 0; p < TPP; p++) {
                float4 h = *reinterpret_cast<const float4*>(sh_buf + p * HID + k);
                float s0 = acc0[p], s1 = acc1[p];
                s0 = fmaf(h.x, A0, s0); s1 = fmaf(h.x, C0, s1);
                s0 = fmaf(h.y, A1, s0); s1 = fmaf(h.y, C1, s1);
                s0 = fmaf(h.z, A2, s0); s1 = fmaf(h.z, C2, s1);
                s0 = fmaf(h.w, A3, s0); s1 = fmaf(h.w, C3, s1);
                acc0[p] = s0; acc1[p] = s1;
            }
            float nB0 = 0.f, nB1 = 0.f, nB2 = 0.f, nB3 = 0.f;
            float nD0 = 0.f, nD1 = 0.f, nD2 = 0.f, nD3 = 0.f;
            if (k + 12 < HID) {
                nB0 = W2[(k + 12) * HID + j0]; nB1 = W2[(k + 13) * HID + j0];
                nB2 = W2[(k + 14) * HID + j0]; nB3 = W2[(k + 15) * HID + j0];
                nD0 = W2[(k + 12) * HID + j1]; nD1 = W2[(k + 13) * HID + j1];
                nD2 = W2[(k + 14) * HID + j1]; nD3 = W2[(k + 15) * HID + j1];
            }
            #pragma unroll
            for (int p = 0; p < TPP; p++) {
                float4 h = *reinterpret_cast<const float4*>(sh_buf + p * HID + k + 4);
                float s0 = acc0[p], s1 = acc1[p];
                s0 = fmaf(h.x, B0, s0); s1 = fmaf(h.x, D0, s1);
                s0 = fmaf(h.y, B1, s0); s1 = fmaf(h.y, D1, s1);
                s0 = fmaf(h.z, B2, s0); s1 = fmaf(h.z, D2, s1);
                s0 = fmaf(h.w, B3, s0); s1 = fmaf(h.w, D3, s1);
                acc0[p] = s0; acc1[p] = s1;
            }
            A0 = nA0; A1 = nA1; A2 = nA2; A3 = nA3;
            C0 = nC0; C1 = nC1; C2 = nC2; C3 = nC3;
            B0 = nB0; B1 = nB1; B2 = nB2; B3 = nB3;
            D0 = nD0; D1 = nD1; D2 = nD2; D3 = nD3;
        }
    } else {
        float a0 = W2[0 * HID + j0], a1 = W2[1 * HID + j0], a2 = W2[2 * HID + j0], a3 = W2[3 * HID + j0];
        float c0 = W2[0 * HID + j1], c1 = W2[1 * HID + j1], c2 = W2[2 * HID + j1], c3 = W2[3 * HID + j1];
        #pragma unroll 1
        for (int k = 0; k < HID; k += 4) {
            float na0 = 0.f, na1 = 0.f, na2 = 0.f, na3 = 0.f;
            float nc0 = 0.f, nc1 = 0.f, nc2 = 0.f, nc3 = 0.f;
            if (k + 4 < HID) {
                na0 = W2[(k + 4) * HID + j0]; na1 = W2[(k + 5) * HID + j0];
                na2 = W2[(k + 6) * HID + j0]; na3 = W2[(k + 7) * HID + j0];
                nc0 = W2[(k + 4) * HID + j1]; nc1 = W2[(k + 5) * HID + j1];
                nc2 = W2[(k + 6) * HID + j1]; nc3 = W2[(k + 7) * HID + j1];
            }
            #pragma unroll
            for (int p = 0; p < TPP; p++) {
                float4 h = *reinterpret_cast<const float4*>(sh_buf + p * HID + k);
                float s0 = acc0[p], s1 = acc1[p];
                s0 = fmaf(h.x, a0, s0); s1 = fmaf(h.x, c0, s1);
                s0 = fmaf(h.y, a1, s0); s1 = fmaf(h.y, c1, s1);
                s0 = fmaf(h.z, a2, s0); s1 = fmaf(h.z, c2, s1);
                s0 = fmaf(h.w, a3, s0); s1 = fmaf(h.w, c3, s1);
                acc0[p] = s0; acc1[p] = s1;
            }
            a0 = na0; a1 = na1; a2 = na2; a3 = na3;
            c0 = nc0; c1 = nc1; c2 = nc2; c3 = nc3;
        }
    }
    __syncthreads();

    // ---- epilogue: h2 = softplus(acc + b2), stored TRANSPOSED (stride TPP+1) ----
    {
        float b20 = b2[j0], b21 = b2[j1];
        #pragma unroll
        for (int p = 0; p < TPP; p++) {
            sh_buf[j0 * H2S + p] = softplus_f(addrn(acc0[p], b20));
            sh_buf[j1 * H2S + p] = softplus_f(addrn(acc1[p], b21));
        }
    }
    __syncthreads();

    // ---- w3 dot: strict ascending-k fmaf chain (one thread per point) ----
    if (t < TPP) {
        const int p = t;
        float s = 0.0f;
        #pragma unroll 8
        for (int j = 0; j < HID; j++)
            s = fmaf(sh_buf[j * H2S + p], sh_w3[j], s);
        float inner = mulrn(0.1f, addrn(s, b3p[0]));
        float4 q = sh_pts[p];
        float n2 = addrn(addrn(addrn(mulrn(q.x, q.x), mulrn(q.y, q.y)),
                               mulrn(q.z, q.z)), 1e-12f);
        sh_out[p] = addrn(subrn(sqrtf(n2), 0.9f), inner);
    }
    __syncthreads();
}

// dispatch on packed active count (TPPMAX = compile-time tile bound)
template<int TPPMAX>
__device__ __forceinline__ void eval_dispatch(int cnt,
    const float4* sh_pts, float* sh_buf, const float* sh_w3, float* sh_out,
    const float* W1, const float* b1, const float* W2, const float* b2,
    const float* b3p)
{
    if (cnt <= 2)      sdf_eval_block<2,  true>(sh_pts, sh_buf, sh_w3, sh_out, W1, b1, W2, b2, b3p);
    else if (cnt <= 4) sdf_eval_block<4,  true>(sh_pts, sh_buf, sh_w3, sh_out, W1, b1, W2, b2, b3p);
    else if (cnt <= 8 || TPPMAX <= 8)
                       sdf_eval_block<8,  true>(sh_pts, sh_buf, sh_w3, sh_out, W1, b1, W2, b2, b3p);
    else               sdf_eval_block<(TPPMAX > 8 ? TPPMAX : 16), true>
                           (sh_pts, sh_buf, sh_w3, sh_out, W1, b1, W2, b2, b3p);
}

#define DECLARE_EVAL_SMEM(TPP)                                    \
    __shared__ float4 sh_pts[TPP];                                \
    __shared__ __align__(16) float sh_buf[HID * ((TPP) + 1)];     \
    __shared__ float sh_w3[HID];                                  \
    __shared__ float sh_sdf[TPP];                                 \
    __shared__ int sh_cnt;

#define LOAD_W3()                                                 \
    do { sh_w3[threadIdx.x] = w3[threadIdx.x];                    \
         sh_w3[threadIdx.x + EVAL_THREADS] = w3[threadIdx.x + EVAL_THREADS]; } while (0)

// shared body of one tracing iteration with active-point repacking.
// TPPMAX <= 32 (ray-owning threads all in warp 0). Bit-identical per ray.
template<int TPPMAX>
__device__ __forceinline__ void trace_one_iter(
    bool vr, int& unf, float& acc, float accend, float& nsdf,
    float cx, float cy, float cz, float dx, float dy, float dz,
    float4* sh_pts, float* sh_buf, const float* sh_w3, float* sh_sdf,
    int* sh_cnt, bool& block_done,
    const float* W1, const float* b1, const float* W2, const float* b2,
    const float* b3p)
{
    const int t = threadIdx.x;
    float csdf = 0.f;
    int slot = 0; bool act = false;

    __syncthreads();   // prior sh_sdf reads complete before sh_pts reuse
    if (t < 32) {
        if (vr) {
            csdf = unf ? nsdf : 0.0f;
            if (csdf <= SDF_THR) csdf = 0.0f;
            unf = unf && (csdf > SDF_THR);
            acc = addrn(acc, csdf);
        }
        act = vr && unf;
        unsigned m = __ballot_sync(0xffffffffu, act);
        slot = __popc(m & ((1u << t) - 1u));
        if (act)
            sh_pts[slot] = make_float4(ray_pt(cx, acc, dx), ray_pt(cy, acc, dy),
                                       ray_pt(cz, acc, dz), 0.0f);
        if (t == 0) sh_cnt[0] = __popc(m);
    }
    __syncthreads();
    int cnt = sh_cnt[0];
    if (cnt == 0) { block_done = true; return; }

    eval_dispatch<TPPMAX>(cnt, sh_pts, sh_buf, sh_w3, sh_sdf, W1, b1, W2, b2, b3p);

    int notproj = 0;
    if (t < 32) {
        if (vr) {
            nsdf = act ? sh_sdf[slot] : 0.0f;
            notproj = (nsdf < 0.0f) ? 1 : 0;
            if (notproj) acc = subrn(acc, mulrn(0.5f, csdf));
        }
        bool act2 = vr && notproj;
        unsigned m2 = __ballot_sync(0xffffffffu, act2);
        int slot2 = __popc(m2 & ((1u << t) - 1u));
        if (act2)
            sh_pts[slot2] = make_float4(ray_pt(cx, acc, dx), ray_pt(cy, acc, dy),
                                        ray_pt(cz, acc, dz), 0.0f);
        if (t == 0) sh_cnt[0] = __popc(m2);
        slot = slot2; act = act2;
    }
    __syncthreads();
    int cnt2 = sh_cnt[0];
    if (cnt2 > 0) {
        eval_dispatch<TPPMAX>(cnt2, sh_pts, sh_buf, sh_w3, sh_sdf, W1, b1, W2, b2, b3p);
        if (t < 32 && act) nsdf = sh_sdf[slot];
    }
    if (vr) unf = unf && (acc < accend);
}

// ---------------- kernels ----------------

// zero counters + detect object_mask dtype from byte patterns
__global__ void reset_kernel(const unsigned char* __restrict__ mb, int nelem) {
    __shared__ int s_nonalign, s_floatok;
    if (threadIdx.x == 0) {
        s_nonalign = 0; s_floatok = 1;
        g_scount = 0; g_seccount = 0; g_tcount = 0;
    }
    __syncthreads();
    int nwords = nelem >> 2;
    const unsigned int* w = (const unsigned int*)mb;
    for (int i = threadIdx.x; i < nwords; i += blockDim.x) {
        unsigned int v = w[i];
        if (v & 0xFFFFFF00u) atomicOr(&s_nonalign, 1);
        if (!(v == 0u || v == 0x3F800000u)) atomicAnd(&s_floatok, 0);
    }
    __syncthreads();
    if (threadIdx.x == 0)
        g_mask_mode = (!s_nonalign) ? 0 : (s_floatok ? 1 : 2);
}

// PHASE A: sphere intersection + initial eval + iterations 0..TRACE_SPLIT-1.
__global__ void __launch_bounds__(EVAL_THREADS, 4)
trace_phaseA_kernel(const float* __restrict__ cam, const float* __restrict__ dirs,
                    const float* __restrict__ W1, const float* __restrict__ b1,
                    const float* __restrict__ W2, const float* __restrict__ b2,
                    const float* __restrict__ w3, const float* __restrict__ b3p,
                    int bn, int nper)
{
    DECLARE_EVAL_SMEM(TPA);
    const int t = threadIdx.x;
    const int r = blockIdx.x * TPA + t;
    const bool vr = (t < TPA) && (r < bn);
    LOAD_W3();

    int unf = 0, slot = 0;
    float acc = 0.f, accend = 0.f, nsdf = 0.f;
    float cx = 0.f, cy = 0.f, cz = 0.f, dx = 0.f, dy = 0.f, dz = 0.f;

    if (t < 32) {
        if (vr) {
            int b = r / nper;
            cx = cam[b * 3]; cy = cam[b * 3 + 1]; cz = cam[b * 3 + 2];
            dx = dirs[r * 3]; dy = dirs[r * 3 + 1]; dz = dirs[r * 3 + 2];
            float dot = addrn(addrn(mulrn(dx, cx), mulrn(dy, cy)), mulrn(dz, cz));
            float c2  = addrn(addrn(mulrn(cx, cx), mulrn(cy, cy)), mulrn(cz, cz));
            float under = subrn(mulrn(dot, dot), subrn(c2, 1.0f));   // R = 1
            int m = (under > 0.0f) ? 1 : 0;
            float d0 = 0.0f, d1 = 0.0f;
            if (m) {
                float s = sqrtf(under);
                d0 = fmaxf(subrn(-s, dot), 0.0f);
                d1 = fmaxf(subrn( s, dot), 0.0f);
            }
            unf = m; acc = d0; accend = d1;
        }
        bool act = (unf != 0);
        unsigned msk = __ballot_sync(0xffffffffu, act);
        slot = __popc(msk & ((1u << t) - 1u));
        if (act)
            sh_pts[slot] = make_float4(ray_pt(cx, acc, dx), ray_pt(cy, acc, dy),
                                       ray_pt(cz, acc, dz), 0.0f);
        if (t == 0) sh_cnt = __popc(msk);
    }
    __syncthreads();
    int cnt = sh_cnt;
    if (cnt > 0)
        eval_dispatch<TPA>(cnt, sh_pts, sh_buf, sh_w3, sh_sdf, W1, b1, W2, b2, b3p);
    if (vr) nsdf = unf ? sh_sdf[slot] : 0.0f;

    bool block_done = (cnt == 0);
    for (int it = 0; it < TRACE_SPLIT && !block_done; ++it)
        trace_one_iter<TPA>(vr, unf, acc, accend, nsdf, cx, cy, cz, dx, dy, dz,
                            sh_pts, sh_buf, sh_w3, sh_sdf, &sh_cnt, block_done,
                            W1, b1, W2, b2, b3p);

    if (vr) {
        g_acc[r] = acc;
        g_accend[r] = accend;
        g_nextsdf[r] = nsdf;
        g_unf[r] = (unsigned char)unf;
    }
}

// compact surviving active rays into g_tlist
__global__ void trace_compact_kernel(int bn) {
    int r = blockIdx.x * blockDim.x + threadIdx.x;
    if (r >= bn) return;
    if (g_unf[r]) {
        int pos = atomicAdd(&g_tcount, 1);
        g_tlist[pos] = r;
    }
}

// PHASE B: iterations TRACE_SPLIT..TRACE_ITERS-1 on packed active list.
__global__ void __launch_bounds__(EVAL_THREADS, 4)
trace_phaseB_kernel(const float* __restrict__ cam, const float* __restrict__ dirs,
                    const float* __restrict__ W1, const float* __restrict__ b1,
                    const float* __restrict__ W2, const float* __restrict__ b2,
                    const float* __restrict__ w3, const float* __restrict__ b3p,
                    int nper)
{
    int cnt = g_tcount;
    int base = blockIdx.x * TPB;
    if (base >= cnt) return;   // uniform early exit
    DECLARE_EVAL_SMEM(TPB);
    const int t = threadIdx.x;
    LOAD_W3();

    bool vr = false;
    int r = 0, unf = 0;
    float acc = 0.f, accend = 0.f, nsdf = 0.f;
    float cx = 0.f, cy = 0.f, cz = 0.f, dx = 0.f, dy = 0.f, dz = 0.f;

    if (t < TPB) {
        int idx = base + t;
        vr = idx < cnt;
        if (vr) {
            r = g_tlist[idx];
            unf = 1;                         // list holds only unfinished rays
            acc = g_acc[r]; accend = g_accend[r]; nsdf = g_nextsdf[r];
            int b = r / nper;
            cx = cam[b * 3]; cy = cam[b * 3 + 1]; cz = cam[b * 3 + 2];
            dx = dirs[r * 3]; dy = dirs[r * 3 + 1]; dz = dirs[r * 3 + 2];
        }
    }

    bool block_done = false;
    for (int it = TRACE_SPLIT; it < TRACE_ITERS && !block_done; ++it)
        trace_one_iter<TPB>(vr, unf, acc, accend, nsdf, cx, cy, cz, dx, dy, dz,
                            sh_pts, sh_buf, sh_w3, sh_sdf, &sh_cnt, block_done,
                            W1, b1, W2, b2, b3p);

    if (vr) {
        g_acc[r] = acc;
        g_nextsdf[r] = nsdf;
        g_unf[r] = (unsigned char)unf;
    }
}

// final mask update, base outputs, sampler-ray compaction
__global__ void finalize_kernel(const float* __restrict__ cam, const float* __restrict__ dirs,
                                float* __restrict__ out_pts, float* __restrict__ out_mask,
                                float* __restrict__ out_dist, int bn, int nper)
{
    int r = blockIdx.x * blockDim.x + threadIdx.x;
    if (r >= bn) return;
    int unf = g_unf[r];
    float cs = unf ? g_nextsdf[r] : 0.0f;
    if (cs <= SDF_THR) cs = 0.0f;
    unf = unf && (cs > SDF_THR);
    float a = g_acc[r], e = g_accend[r];
    int b = r / nper;
    float cx = cam[b * 3], cy = cam[b * 3 + 1], cz = cam[b * 3 + 2];
    float dx = dirs[r * 3], dy = dirs[r * 3 + 1], dz = dirs[r * 3 + 2];
    out_pts[r * 3 + 0] = ray_pt(cx, a, dx);
    out_pts[r * 3 + 1] = ray_pt(cy, a, dy);
    out_pts[r * 3 + 2] = ray_pt(cz, a, dz);
    out_mask[r] = (a < e) ? 1.0f : 0.0f;
    out_dist[r] = a;
    if (unf) {
        int pos = atomicAdd(&g_scount, 1);
        g_slist[pos] = r;
    }
}

// evaluate sdf on the 100-step march of every sampler ray (compacted)
__global__ void __launch_bounds__(EVAL_THREADS)
sampler_eval_kernel(const float* __restrict__ cam, const float* __restrict__ dirs,
                    const float* __restrict__ W1, const float* __restrict__ b1,
                    const float* __restrict__ W2, const float* __restrict__ b2,
                    const float* __restrict__ w3, const float* __restrict__ b3p,
                    int nper)
{
    int total = g_scount * NSTEPS;
    int base = blockIdx.x * TPS;
    if (base >= total) return;  // uniform across the block
    DECLARE_EVAL_SMEM(TPS);
    int t = threadIdx.x;
    int q = base + t;
    bool valid = false;
    LOAD_W3();
    if (t < TPS) {
        valid = q < total;
        if (valid) {
            int slot = q / NSTEPS;
            int s = q - slot * NSTEPS;
            int r = g_slist[slot];
            float a = g_acc[r], e = g_accend[r];
            float d = addrn(a, mulrn(lin_t(s), subrn(e, a)));
            int b = r / nper;
            sh_pts[t] = make_float4(ray_pt(cam[b * 3 + 0], d, dirs[r * 3 + 0]),
                                    ray_pt(cam[b * 3 + 1], d, dirs[r * 3 + 1]),
                                    ray_pt(cam[b * 3 + 2], d, dirs[r * 3 + 2]), 0.0f);
        } else {
            sh_pts[t] = make_float4(0.0f, 0.0f, 0.0f, 0.0f);
        }
    }
    __syncthreads();
    sdf_eval_block<TPS, false>(sh_pts, sh_buf, sh_w3, sh_sdf, W1, b1, W2, b2, b3p);
    if (t < TPS && valid) g_sdf100[q] = sh_sdf[t];
}

// argmin selection, sampler outputs, secant-ray compaction
__global__ void select_kernel(const float* __restrict__ cam, const float* __restrict__ dirs,
                              const void* __restrict__ omask,
                              float* __restrict__ out_pts, float* __restrict__ out_mask,
                              float* __restrict__ out_dist, int nper)
{
    int cnt = g_scount;
    for (int slot = blockIdx.x * blockDim.x + threadIdx.x; slot < cnt;
         slot += gridDim.x * blockDim.x) {
        int r = g_slist[slot];
        const float* base = &g_sdf100[slot * NSTEPS];
        float bestt = 1e30f; int ind = 0;
        float bestv = 1e30f; int oind = 0;
        for (int i = 0; i < NSTEPS; i++) {
            float v = base[i];
            float sgn = (v > 0.0f) ? 1.0f : ((v < 0.0f) ? -1.0f : 0.0f);
            float tmp = sgn * (float)(NSTEPS - i);
            if (tmp < bestt) { bestt = tmp; ind = i; }      // first-occurrence argmin
            if (v   < bestv) { bestv = v;   oind = i; }
        }
        bool net = base[ind] < 0.0f;
        bool obj = read_mask(omask, r);
        bool p_out = !(obj && net);
        int ind2 = p_out ? oind : ind;
        float a = g_acc[r], e = g_accend[r];
        int b = r / nper;
        float cx = cam[b * 3], cy = cam[b * 3 + 1], cz = cam[b * 3 + 2];
        float dx = dirs[r * 3], dy = dirs[r * 3 + 1], dz = dirs[r * 3 + 2];
        float d2 = addrn(a, mulrn(lin_t(ind2), subrn(e, a)));
        out_pts[r * 3 + 0] = ray_pt(cx, d2, dx);
        out_pts[r * 3 + 1] = ray_pt(cy, d2, dy);
        out_pts[r * 3 + 2] = ray_pt(cz, d2, dz);
        out_dist[r] = d2;
        out_mask[r] = net ? 1.0f : 0.0f;
        if (net && obj) {
            int im1 = (ind == 0) ? (NSTEPS - 1) : (ind - 1);   // torch (-1) wrap
            g_zh[r]  = addrn(a, mulrn(lin_t(ind), subrn(e, a)));
            g_shh[r] = base[ind];
            g_zl[r]  = addrn(a, mulrn(lin_t(im1), subrn(e, a)));
            g_sl[r]  = base[im1];
            int pos = atomicAdd(&g_seccount, 1);
            g_seclist[pos] = r;
        }
    }
}

// FUSED: all 8 secant iterations in one kernel (blocks over compacted rays)
__global__ void __launch_bounds__(EVAL_THREADS, 4)
secant_fused_kernel(const float* __restrict__ cam, const float* __restrict__ dirs,
                    const float* __restrict__ W1, const float* __restrict__ b1,
                    const float* __restrict__ W2, const float* __restrict__ b2,
                    const float* __restrict__ w3, const float* __restrict__ b3p,
                    float* __restrict__ out_pts, float* __restrict__ out_dist,
                    int nper)
{
    int cnt = g_seccount;
    int base = blockIdx.x * SECTP;
    if (base >= cnt) return;  // uniform
    DECLARE_EVAL_SMEM(SECTP);
    int t = threadIdx.x;
    bool valid = false;
    int r = 0;
    float zl = 0.f, zh = 0.f, sl = 0.f, shv = 0.f;
    float cx = 0.f, cy = 0.f, cz = 0.f, dx = 0.f, dy = 0.f, dz = 0.f;
    LOAD_W3();
    if (t < SECTP) {
        int idx = base + t;
        valid = idx < cnt;
        if (valid) {
            r = g_seclist[idx];
            zl = g_zl[r]; zh = g_zh[r]; sl = g_sl[r]; shv = g_shh[r];
            int b = r / nper;
            cx = cam[b * 3]; cy = cam[b * 3 + 1]; cz = cam[b * 3 + 2];
            dx = dirs[r * 3]; dy = dirs[r * 3 + 1]; dz = dirs[r * 3 + 2];
        }
        sh_pts[t] = make_float4(0.0f, 0.0f, 0.0f, 0.0f);
    }

    for (int it = 0; it < SECANT_ITERS; ++it) {
        float zp = 0.f;
        if (valid) {
            float den = subrn(shv, sl);
            if (den == 0.0f) den = 1.0f;
            zp = addrn(divrn(mulrn(-sl, subrn(zh, zl)), den), zl);
            sh_pts[t] = make_float4(ray_pt(cx, zp, dx), ray_pt(cy, zp, dy),
                                    ray_pt(cz, zp, dz), 0.0f);
        }
        __syncthreads();
        sdf_eval_block<SECTP, true>(sh_pts, sh_buf, sh_w3, sh_sdf, W1, b1, W2, b2, b3p);
        if (valid) {
            float mid = sh_sdf[t];
            if (mid > 0.0f) { zl = zp; sl = mid; }
            if (mid < 0.0f) { zh = zp; shv = mid; }
        }
    }

    // final secant prediction + output override
    if (valid) {
        float den = subrn(shv, sl);
        if (den == 0.0f) den = 1.0f;
        float zp = addrn(divrn(mulrn(-sl, subrn(zh, zl)), den), zl);
        out_pts[r * 3 + 0] = ray_pt(cx, zp, dx);
        out_pts[r * 3 + 1] = ray_pt(cy, zp, dy);
        out_pts[r * 3 + 2] = ray_pt(cz, zp, dz);
        out_dist[r] = zp;
    }
}

// ---------------- host launcher ----------------
extern "C" void kernel_launch(void* const* d_in, const int* in_sizes, int n_in,
                              void* d_out, int out_size)
{
    const float* cam  = (const float*)d_in[0];
    const void*  om   = d_in[1];
    const float* dirs = (const float*)d_in[2];
    const float* W1   = (const float*)d_in[3];
    const float* b1   = (const float*)d_in[4];
    const float* W2   = (const float*)d_in[5];
    const float* b2   = (const float*)d_in[6];
    const float* w3   = (const float*)d_in[7];
    const float* b3   = (const float*)d_in[8];

    int bn   = in_sizes[2] / 3;        // total rays (B*N)
    int ncam = in_sizes[0] / 3;        // B
    int nper = bn / ncam;              // N

    float* out      = (float*)d_out;
    float* out_pts  = out;             // [bn,3]
    float* out_mask = out + 3 * bn;    // [bn]
    float* out_dist = out + 4 * bn;    // [bn]

    int nba = (bn + TPA - 1) / TPA;    // phase A blocks (256)
    int nbb = (bn + TPB - 1) / TPB;    // phase B max blocks (512)
    int nbs = (bn + SECTP - 1) / SECTP; // secant max blocks (1024)

    reset_kernel<<<1, 256>>>((const unsigned char*)om, bn);
    trace_phaseA_kernel<<<nba, EVAL_THREADS>>>(cam, dirs, W1, b1, W2, b2, w3, b3, bn, nper);
    trace_compact_kernel<<<(bn + 255) / 256, 256>>>(bn);
    trace_phaseB_kernel<<<nbb, EVAL_THREADS>>>(cam, dirs, W1, b1, W2, b2, w3, b3, nper);
    finalize_kernel<<<(bn + 255) / 256, 256>>>(cam, dirs, out_pts, out_mask, out_dist, bn, nper);

    int nsb = (bn * NSTEPS + TPS - 1) / TPS;   // max sampler blocks; early-exit on count
    sampler_eval_kernel<<<nsb, EVAL_THREADS>>>(cam, dirs, W1, b1, W2, b2, w3, b3, nper);
    select_kernel<<<32, 128>>>(cam, dirs, om, out_pts, out_mask, out_dist, nper);

    secant_fused_kernel<<<nbs, EVAL_THREADS>>>(cam, dirs, W1, b1, W2, b2, w3, b3,
                                               out_pts, out_dist, nper);
}